// round 4
// baseline (speedup 1.0000x reference)
#include <cuda_runtime.h>
#include <math.h>

#define NMAX 50000
#define EMAX 800000
#define D 128

// ---------------- scratch (device globals; no allocation allowed) ----------
__device__ int   g_is64;
__device__ int   g_src[EMAX];
__device__ int   g_dst[EMAX];
__device__ float g_norm[EMAX];
__device__ float g_deg[NMAX];
__device__ float g_dinv[NMAX];
__device__ float g_h[NMAX * D];
__device__ float g_agg[NMAX * D];
__device__ float g_x[NMAX * D];
__device__ float g_y1[NMAX * 256];

// ---------------- helpers ---------------------------------------------------
__device__ __forceinline__ float getc(const float4& v, int i) {
    switch (i & 3) {
        case 0: return v.x;
        case 1: return v.y;
        case 2: return v.z;
        default: return v.w;
    }
}

__device__ __forceinline__ float leaky1(float v) {
    return v >= 0.0f ? v : 0.01f * v;
}

// ---------------- edge-index width detection -------------------------------
// Node ids are in [0, 50000). If edge_index is int64, the high 32-bit word of
// every entry is 0. If int32, those words are src values (prob of 1024 zeros
// is ~0 for random ids). 32 threads scan 1024 entries cooperatively.
__global__ void detect_k(const unsigned int* __restrict__ w, int E) {
    __shared__ int nz;
    if (threadIdx.x == 0) nz = 0;
    __syncthreads();
    int n = E < 1024 ? E : 1024;
    for (int i = threadIdx.x; i < n; i += 32)
        if (w[2 * i + 1] != 0u) atomicAdd(&nz, 1);
    __syncthreads();
    if (threadIdx.x == 0) g_is64 = (nz == 0) ? 1 : 0;
}

__global__ void convert_k(const void* __restrict__ ei, int E) {
    int e = blockIdx.x * blockDim.x + threadIdx.x;
    if (e >= E) return;
    if (g_is64) {
        const long long* p = (const long long*)ei;
        g_src[e] = (int)p[e];
        g_dst[e] = (int)p[E + e];
    } else {
        const int* p = (const int*)ei;
        g_src[e] = p[e];
        g_dst[e] = p[E + e];
    }
}

// ---------------- degree / normalization ------------------------------------
__global__ void deg_init_k(int N) {
    int i = blockIdx.x * blockDim.x + threadIdx.x;
    if (i < N) g_deg[i] = 1.0f;  // self loop
}

__global__ void deg_count_k(int E) {
    int e = blockIdx.x * blockDim.x + threadIdx.x;
    if (e < E) atomicAdd(&g_deg[g_dst[e]], 1.0f);
}

__global__ void dinv_k(int N) {
    int i = blockIdx.x * blockDim.x + threadIdx.x;
    if (i < N) g_dinv[i] = rsqrtf(g_deg[i]);
}

__global__ void norm_k(int E) {
    int e = blockIdx.x * blockDim.x + threadIdx.x;
    if (e < E) g_norm[e] = g_dinv[g_src[e]] * g_dinv[g_dst[e]];
}

// ---------------- GEMM: H = X @ W  (K = 128 fixed) ---------------------------
// W ([128, NOUT]) lives in shared. Each warp computes RPW rows; each lane owns
// NOUT/128 float4 column chunks. X rows register-resident, shfl-broadcast.
// If SELFLOOP: also writes AGG = dinv[row]^2 * H (pre-activation).
// If DOLEAKY: writes leaky(H).
template <int NOUT, int RPW, bool DOLEAKY, bool SELFLOOP>
__global__ void gemm_k(const float* __restrict__ X, const float* __restrict__ W,
                       float* __restrict__ H, float* __restrict__ AGG,
                       const float* __restrict__ dinv, int N) {
    extern __shared__ float4 Ws4[];  // D*NOUT floats
    const float4* W4 = (const float4*)W;
    for (int i = threadIdx.x; i < D * NOUT / 4; i += blockDim.x) Ws4[i] = W4[i];
    __syncthreads();

    constexpr int C = NOUT / 128;  // float4 column chunks per lane
    int lane = threadIdx.x & 31;
    int warp_g = blockIdx.x * (blockDim.x >> 5) + (threadIdx.x >> 5);
    int row0 = warp_g * RPW;
    if (row0 >= N) return;

    float4 xr[RPW];
#pragma unroll
    for (int r = 0; r < RPW; r++) {
        int row = row0 + r;
        xr[r] = (row < N) ? ((const float4*)(X + (size_t)row * D))[lane]
                          : make_float4(0.f, 0.f, 0.f, 0.f);
    }

    float4 acc[RPW][C];
#pragma unroll
    for (int r = 0; r < RPW; r++)
#pragma unroll
        for (int c = 0; c < C; c++) acc[r][c] = make_float4(0.f, 0.f, 0.f, 0.f);

    for (int sl = 0; sl < 32; ++sl) {
        float4 xs[RPW];
#pragma unroll
        for (int r = 0; r < RPW; r++) {
            xs[r].x = __shfl_sync(0xffffffffu, xr[r].x, sl);
            xs[r].y = __shfl_sync(0xffffffffu, xr[r].y, sl);
            xs[r].z = __shfl_sync(0xffffffffu, xr[r].z, sl);
            xs[r].w = __shfl_sync(0xffffffffu, xr[r].w, sl);
        }
        int kb = sl * 4;
#pragma unroll
        for (int kk = 0; kk < 4; kk++) {
            float4 wv[C];
#pragma unroll
            for (int c = 0; c < C; c++)
                wv[c] = Ws4[(size_t)(kb + kk) * (NOUT / 4) + lane + 32 * c];
#pragma unroll
            for (int r = 0; r < RPW; r++) {
                float xv = getc(xs[r], kk);
#pragma unroll
                for (int c = 0; c < C; c++) {
                    acc[r][c].x += xv * wv[c].x;
                    acc[r][c].y += xv * wv[c].y;
                    acc[r][c].z += xv * wv[c].z;
                    acc[r][c].w += xv * wv[c].w;
                }
            }
        }
    }

#pragma unroll
    for (int r = 0; r < RPW; r++) {
        int row = row0 + r;
        if (row >= N) continue;
        float s2 = 0.f;
        if (SELFLOOP) {
            float s = dinv[row];
            s2 = s * s;
        }
#pragma unroll
        for (int c = 0; c < C; c++) {
            float4 v = acc[r][c];
            if (SELFLOOP) {
                float4 a;
                a.x = s2 * v.x; a.y = s2 * v.y; a.z = s2 * v.z; a.w = s2 * v.w;
                ((float4*)(AGG + (size_t)row * NOUT))[lane + 32 * c] = a;
            }
            if (DOLEAKY) {
                v.x = leaky1(v.x); v.y = leaky1(v.y);
                v.z = leaky1(v.z); v.w = leaky1(v.w);
            }
            ((float4*)(H + (size_t)row * NOUT))[lane + 32 * c] = v;
        }
    }
}

// ---------------- scatter: AGG[dst] += norm * H[src] -------------------------
// One warp per edge: 32 lanes x float4 = the full 128-float row.
__global__ void scatter_k(const float* __restrict__ H, float* __restrict__ AGG,
                          int E) {
    int lane = threadIdx.x & 31;
    int e = blockIdx.x * (blockDim.x >> 5) + (threadIdx.x >> 5);
    if (e >= E) return;
    int s = g_src[e];
    int d = g_dst[e];
    float w = g_norm[e];
    float4 v = ((const float4*)(H + (size_t)s * D))[lane];
    v.x *= w; v.y *= w; v.z *= w; v.w *= w;
    float* p = AGG + (size_t)d * D + lane * 4;
    asm volatile("red.global.add.v4.f32 [%0], {%1, %2, %3, %4};"
                 :: "l"(p), "f"(v.x), "f"(v.y), "f"(v.z), "f"(v.w)
                 : "memory");
}

// ---------------- elementwise leaky ------------------------------------------
__global__ void leaky_k(const float4* __restrict__ in, float4* __restrict__ out,
                        int n4) {
    int i = blockIdx.x * blockDim.x + threadIdx.x;
    if (i >= n4) return;
    float4 v = in[i];
    v.x = leaky1(v.x); v.y = leaky1(v.y); v.z = leaky1(v.z); v.w = leaky1(v.w);
    out[i] = v;
}

// ---------------- fc2 (256 -> 2) + leaky + softmax ---------------------------
__global__ void fc2_softmax_k(const float* __restrict__ Y,
                              const float* __restrict__ W2,
                              float* __restrict__ out, int N) {
    __shared__ float w0[256], w1[256];
    for (int i = threadIdx.x; i < 256; i += blockDim.x) {
        w0[i] = W2[i * 2];
        w1[i] = W2[i * 2 + 1];
    }
    __syncthreads();
    int lane = threadIdx.x & 31;
    int node = blockIdx.x * (blockDim.x >> 5) + (threadIdx.x >> 5);
    if (node >= N) return;
    float a0 = 0.f, a1 = 0.f;
#pragma unroll
    for (int i = 0; i < 8; i++) {
        int k = lane + 32 * i;
        float y = Y[(size_t)node * 256 + k];
        a0 += y * w0[k];
        a1 += y * w1[k];
    }
#pragma unroll
    for (int o = 16; o; o >>= 1) {
        a0 += __shfl_xor_sync(0xffffffffu, a0, o);
        a1 += __shfl_xor_sync(0xffffffffu, a1, o);
    }
    if (lane == 0) {
        a0 = leaky1(a0);
        a1 = leaky1(a1);
        float m = fmaxf(a0, a1);
        float e0 = expf(a0 - m), e1 = expf(a1 - m);
        float inv = 1.0f / (e0 + e1);
        out[(size_t)node * 2 + 0] = e0 * inv;
        out[(size_t)node * 2 + 1] = e1 * inv;
    }
}

// ---------------- launch ------------------------------------------------------
extern "C" void kernel_launch(void* const* d_in, const int* in_sizes, int n_in,
                              void* d_out, int out_size) {
    const float* x    = (const float*)d_in[0];
    const void*  ei   = d_in[1];
    const float* Wg0  = (const float*)d_in[2];
    const float* Wg1  = (const float*)d_in[3];
    const float* Wg2  = (const float*)d_in[4];
    const float* Wfc1 = (const float*)d_in[5];
    const float* Wfc2 = (const float*)d_in[6];
    float* out = (float*)d_out;

    int N = in_sizes[0] / D;
    int E = in_sizes[1] / 2;

    float *p_h, *p_agg, *p_x, *p_y1, *p_dinv;
    cudaGetSymbolAddress((void**)&p_h, g_h);
    cudaGetSymbolAddress((void**)&p_agg, g_agg);
    cudaGetSymbolAddress((void**)&p_x, g_x);
    cudaGetSymbolAddress((void**)&p_y1, g_y1);
    cudaGetSymbolAddress((void**)&p_dinv, g_dinv);

    cudaFuncSetAttribute(gemm_k<128, 8, false, true>,
                         cudaFuncAttributeMaxDynamicSharedMemorySize,
                         D * 128 * 4);
    cudaFuncSetAttribute(gemm_k<256, 4, true, false>,
                         cudaFuncAttributeMaxDynamicSharedMemorySize,
                         D * 256 * 4);

    int tpb = 256;
    int gE = (E + tpb - 1) / tpb;
    int gN = (N + tpb - 1) / tpb;

    detect_k<<<1, 32>>>((const unsigned int*)ei, E);
    convert_k<<<gE, tpb>>>(ei, E);
    deg_init_k<<<gN, tpb>>>(N);
    deg_count_k<<<gE, tpb>>>(E);
    dinv_k<<<gN, tpb>>>(N);
    norm_k<<<gE, tpb>>>(E);

    int gb128 = (N + 63) / 64;            // 8 warps * 8 rows per block
    int gsc   = (E + 7) / 8;              // 1 warp per edge, 8 warps/block
    int n4    = N * D / 4;
    int gl    = (n4 + tpb - 1) / tpb;

    const float* Wg[3] = {Wg0, Wg1, Wg2};
    const float* cur = x;
    for (int l = 0; l < 3; l++) {
        gemm_k<128, 8, false, true><<<gb128, tpb, D * 128 * 4>>>(
            cur, Wg[l], p_h, p_agg, p_dinv, N);
        scatter_k<<<gsc, tpb>>>(p_h, p_agg, E);
        leaky_k<<<gl, tpb>>>((const float4*)p_agg, (float4*)p_x, n4);
        cur = p_x;
    }

    int gb256 = (N + 31) / 32;            // 8 warps * 4 rows per block
    gemm_k<256, 4, true, false><<<gb256, tpb, D * 256 * 4>>>(
        cur, Wfc1, p_y1, nullptr, nullptr, N);

    int gfc = (N + 7) / 8;                // 1 warp per node
    fc2_softmax_k<<<gfc, tpb>>>(p_y1, Wfc2, out, N);
}

// round 5
// speedup vs baseline: 1.3417x; 1.3417x over previous
#include <cuda_runtime.h>
#include <math.h>

#define NMAX 50000
#define EMAX 800000
#define D 128

// ---------------- scratch (device globals; no allocation allowed) ----------
__device__ int    g_is64;
__device__ int    g_degi[NMAX];
__device__ int    g_off[NMAX + 1];
__device__ int    g_cur[NMAX];
__device__ float  g_dinv[NMAX];
__device__ float2 g_emeta[EMAX];   // {src (bitcast int), norm}
__device__ float  g_h[NMAX * D];
__device__ float  g_x[NMAX * D];
__device__ float  g_y1[NMAX * 256];

// ---------------- f32x2 helpers (Blackwell packed fp32) ---------------------
__device__ __forceinline__ unsigned long long pk2(float lo, float hi) {
    unsigned long long d;
    asm("mov.b64 %0, {%1, %2};" : "=l"(d) : "f"(lo), "f"(hi));
    return d;
}
__device__ __forceinline__ float2 upk2(unsigned long long v) {
    float2 r;
    asm("mov.b64 {%0, %1}, %2;" : "=f"(r.x), "=f"(r.y) : "l"(v));
    return r;
}
__device__ __forceinline__ unsigned long long fma2(unsigned long long a,
                                                   unsigned long long b,
                                                   unsigned long long c) {
    unsigned long long d;
    asm("fma.rn.f32x2 %0, %1, %2, %3;" : "=l"(d) : "l"(a), "l"(b), "l"(c));
    return d;
}

__device__ __forceinline__ float leaky1(float v) {
    return v >= 0.0f ? v : 0.01f * v;
}

// ---------------- edge-index width detection -------------------------------
// Ids < 50000, so if int64 every high 32-bit word of the first 1024 entries
// is 0; if int32 those words are src values (all-zero prob ~0).
__global__ void detect_k(const unsigned int* __restrict__ w, int E) {
    __shared__ int nz;
    if (threadIdx.x == 0) nz = 0;
    __syncthreads();
    int n = E < 1024 ? E : 1024;
    for (int i = threadIdx.x; i < n; i += 32)
        if (w[2 * i + 1] != 0u) atomicAdd(&nz, 1);
    __syncthreads();
    if (threadIdx.x == 0) g_is64 = (nz == 0) ? 1 : 0;
}

// ---------------- degree histogram (dst only; self loop handled analytically)
__global__ void count_k(const void* __restrict__ ei, int E) {
    int e = blockIdx.x * blockDim.x + threadIdx.x;
    if (e >= E) return;
    int dst;
    if (g_is64) dst = (int)((const unsigned int*)ei)[2 * (E + e)];
    else        dst = ((const int*)ei)[E + e];
    atomicAdd(&g_degi[dst], 1);
}

__global__ void dinv_k(int N) {
    int i = blockIdx.x * blockDim.x + threadIdx.x;
    if (i < N) g_dinv[i] = rsqrtf((float)g_degi[i] + 1.0f);  // + self loop
}

// ---------------- exclusive scan of degrees -> CSR offsets (1 block) --------
__global__ void scan_k(int N) {
    __shared__ int part[1024];
    int t = threadIdx.x;
    int chunk = (N + 1023) / 1024;
    int b = t * chunk;
    int e = b + chunk < N ? b + chunk : N;
    int s = 0;
    for (int i = b; i < e; i++) s += g_degi[i];
    part[t] = s;
    __syncthreads();
    for (int off = 1; off < 1024; off <<= 1) {
        int v = (t >= off) ? part[t - off] : 0;
        __syncthreads();
        part[t] += v;
        __syncthreads();
    }
    int run = t ? part[t - 1] : 0;
    for (int i = b; i < e; i++) {
        g_off[i] = run;
        g_cur[i] = run;
        run += g_degi[i];
    }
    if (t == 1023) g_off[N] = part[1023];
}

// ---------------- CSR fill: bucket edges by dst -----------------------------
__global__ void fill_k(const void* __restrict__ ei, int E) {
    int e = blockIdx.x * blockDim.x + threadIdx.x;
    if (e >= E) return;
    int src, dst;
    if (g_is64) {
        src = (int)((const unsigned int*)ei)[2 * e];
        dst = (int)((const unsigned int*)ei)[2 * (E + e)];
    } else {
        src = ((const int*)ei)[e];
        dst = ((const int*)ei)[E + e];
    }
    float norm = g_dinv[src] * g_dinv[dst];
    int p = atomicAdd(&g_cur[dst], 1);
    g_emeta[p] = make_float2(__int_as_float(src), norm);
}

// ---------------- GEMM: H = X @ W  (K = 128), packed f32x2 ------------------
// W [128, NOUT] in shared. Each warp computes RPW rows as RPW/2 packed row
// pairs; each lane owns NOUT/32 scalar cols (NOUT/128 float4 chunks).
template <int NOUT, int RPW, bool DOLEAKY>
__global__ void gemm_k(const float* __restrict__ X, const float* __restrict__ W,
                       float* __restrict__ H, int N) {
    extern __shared__ float4 Ws4[];  // D*NOUT floats
    const float4* W4 = (const float4*)W;
    for (int i = threadIdx.x; i < D * NOUT / 4; i += blockDim.x) Ws4[i] = W4[i];
    __syncthreads();

    constexpr int C4 = NOUT / 128;   // float4 col chunks per lane
    constexpr int P  = RPW / 2;      // row pairs
    int lane = threadIdx.x & 31;
    int warp_g = blockIdx.x * (blockDim.x >> 5) + (threadIdx.x >> 5);
    int row0 = warp_g * RPW;
    if (row0 >= N) return;

    // Load x rows, pack row pairs at each of this lane's 4 k slots.
    unsigned long long xp[P][4];
#pragma unroll
    for (int p = 0; p < P; p++) {
        int r0 = row0 + 2 * p, r1 = r0 + 1;
        float4 a = (r0 < N) ? ((const float4*)(X + (size_t)r0 * D))[lane]
                            : make_float4(0.f, 0.f, 0.f, 0.f);
        float4 b = (r1 < N) ? ((const float4*)(X + (size_t)r1 * D))[lane]
                            : make_float4(0.f, 0.f, 0.f, 0.f);
        xp[p][0] = pk2(a.x, b.x);
        xp[p][1] = pk2(a.y, b.y);
        xp[p][2] = pk2(a.z, b.z);
        xp[p][3] = pk2(a.w, b.w);
    }

    unsigned long long acc[P][4 * C4];
#pragma unroll
    for (int p = 0; p < P; p++)
#pragma unroll
        for (int c = 0; c < 4 * C4; c++) acc[p][c] = 0ull;

    for (int sl = 0; sl < 32; ++sl) {
#pragma unroll
        for (int kl = 0; kl < 4; kl++) {
            unsigned long long xs[P];
#pragma unroll
            for (int p = 0; p < P; p++)
                xs[p] = __shfl_sync(0xffffffffu, xp[p][kl], sl);
            int k = sl * 4 + kl;
#pragma unroll
            for (int c = 0; c < C4; c++) {
                float4 wv = Ws4[(size_t)k * (NOUT / 4) + lane + 32 * c];
                unsigned long long w0 = pk2(wv.x, wv.x);
                unsigned long long w1 = pk2(wv.y, wv.y);
                unsigned long long w2 = pk2(wv.z, wv.z);
                unsigned long long w3 = pk2(wv.w, wv.w);
#pragma unroll
                for (int p = 0; p < P; p++) {
                    acc[p][4 * c + 0] = fma2(xs[p], w0, acc[p][4 * c + 0]);
                    acc[p][4 * c + 1] = fma2(xs[p], w1, acc[p][4 * c + 1]);
                    acc[p][4 * c + 2] = fma2(xs[p], w2, acc[p][4 * c + 2]);
                    acc[p][4 * c + 3] = fma2(xs[p], w3, acc[p][4 * c + 3]);
                }
            }
        }
    }

#pragma unroll
    for (int p = 0; p < P; p++) {
        int r0 = row0 + 2 * p, r1 = r0 + 1;
#pragma unroll
        for (int c = 0; c < C4; c++) {
            float2 c0 = upk2(acc[p][4 * c + 0]);
            float2 c1 = upk2(acc[p][4 * c + 1]);
            float2 c2 = upk2(acc[p][4 * c + 2]);
            float2 c3 = upk2(acc[p][4 * c + 3]);
            float4 v0 = make_float4(c0.x, c1.x, c2.x, c3.x);
            float4 v1 = make_float4(c0.y, c1.y, c2.y, c3.y);
            if (DOLEAKY) {
                v0.x = leaky1(v0.x); v0.y = leaky1(v0.y);
                v0.z = leaky1(v0.z); v0.w = leaky1(v0.w);
                v1.x = leaky1(v1.x); v1.y = leaky1(v1.y);
                v1.z = leaky1(v1.z); v1.w = leaky1(v1.w);
            }
            if (r0 < N) ((float4*)(H + (size_t)r0 * NOUT))[lane + 32 * c] = v0;
            if (r1 < N) ((float4*)(H + (size_t)r1 * NOUT))[lane + 32 * c] = v1;
        }
    }
}

// ---------------- gather: X[i] = leaky(dinv_i^2*H[i] + sum norm*H[src]) -----
// One warp per node; lanes hold the 128-float row as float4.
__global__ void gather_k(const float* __restrict__ H, float* __restrict__ X,
                         int N) {
    int lane = threadIdx.x & 31;
    int node = blockIdx.x * (blockDim.x >> 5) + (threadIdx.x >> 5);
    if (node >= N) return;
    int beg = g_off[node], end = g_off[node + 1];
    float s = g_dinv[node];
    float w0 = s * s;
    float4 acc = ((const float4*)(H + (size_t)node * D))[lane];
    acc.x *= w0; acc.y *= w0; acc.z *= w0; acc.w *= w0;

    int j = beg;
    float2 m = (j < end) ? g_emeta[j] : make_float2(0.f, 0.f);
    while (j < end) {
        float2 mn = (j + 1 < end) ? g_emeta[j + 1] : m;
        int src = __float_as_int(m.x);
        float w = m.y;
        float4 v = ((const float4*)(H + (size_t)src * D))[lane];
        acc.x += w * v.x; acc.y += w * v.y;
        acc.z += w * v.z; acc.w += w * v.w;
        m = mn;
        j++;
    }
    acc.x = leaky1(acc.x); acc.y = leaky1(acc.y);
    acc.z = leaky1(acc.z); acc.w = leaky1(acc.w);
    ((float4*)(X + (size_t)node * D))[lane] = acc;
}

// ---------------- fc2 (256 -> 2) + leaky + softmax ---------------------------
__global__ void fc2_softmax_k(const float* __restrict__ Y,
                              const float* __restrict__ W2,
                              float* __restrict__ out, int N) {
    __shared__ float w0[256], w1[256];
    for (int i = threadIdx.x; i < 256; i += blockDim.x) {
        w0[i] = W2[i * 2];
        w1[i] = W2[i * 2 + 1];
    }
    __syncthreads();
    int lane = threadIdx.x & 31;
    int node = blockIdx.x * (blockDim.x >> 5) + (threadIdx.x >> 5);
    if (node >= N) return;
    float a0 = 0.f, a1 = 0.f;
#pragma unroll
    for (int i = 0; i < 8; i++) {
        int k = lane + 32 * i;
        float y = Y[(size_t)node * 256 + k];
        a0 += y * w0[k];
        a1 += y * w1[k];
    }
#pragma unroll
    for (int o = 16; o; o >>= 1) {
        a0 += __shfl_xor_sync(0xffffffffu, a0, o);
        a1 += __shfl_xor_sync(0xffffffffu, a1, o);
    }
    if (lane == 0) {
        a0 = leaky1(a0);
        a1 = leaky1(a1);
        float m = fmaxf(a0, a1);
        float e0 = expf(a0 - m), e1 = expf(a1 - m);
        float inv = 1.0f / (e0 + e1);
        out[(size_t)node * 2 + 0] = e0 * inv;
        out[(size_t)node * 2 + 1] = e1 * inv;
    }
}

// ---------------- launch ------------------------------------------------------
extern "C" void kernel_launch(void* const* d_in, const int* in_sizes, int n_in,
                              void* d_out, int out_size) {
    const float* x    = (const float*)d_in[0];
    const void*  ei   = d_in[1];
    const float* Wg0  = (const float*)d_in[2];
    const float* Wg1  = (const float*)d_in[3];
    const float* Wg2  = (const float*)d_in[4];
    const float* Wfc1 = (const float*)d_in[5];
    const float* Wfc2 = (const float*)d_in[6];
    float* out = (float*)d_out;

    int N = in_sizes[0] / D;
    int E = in_sizes[1] / 2;

    float *p_h, *p_x, *p_y1;
    int* p_degi;
    cudaGetSymbolAddress((void**)&p_h, g_h);
    cudaGetSymbolAddress((void**)&p_x, g_x);
    cudaGetSymbolAddress((void**)&p_y1, g_y1);
    cudaGetSymbolAddress((void**)&p_degi, g_degi);

    cudaFuncSetAttribute(gemm_k<128, 8, false>,
                         cudaFuncAttributeMaxDynamicSharedMemorySize,
                         D * 128 * 4);
    cudaFuncSetAttribute(gemm_k<256, 4, true>,
                         cudaFuncAttributeMaxDynamicSharedMemorySize,
                         D * 256 * 4);

    int tpb = 256;
    int gE = (E + tpb - 1) / tpb;
    int gN = (N + tpb - 1) / tpb;

    // ---- CSR build (once per call) ----
    cudaMemsetAsync(p_degi, 0, (size_t)N * sizeof(int));
    detect_k<<<1, 32>>>((const unsigned int*)ei, E);
    count_k<<<gE, tpb>>>(ei, E);
    dinv_k<<<gN, tpb>>>(N);
    scan_k<<<1, 1024>>>(N);
    fill_k<<<gE, tpb>>>(ei, E);

    // ---- 3 GCN layers ----
    int gb128 = (N + 63) / 64;   // 8 warps * 8 rows per block
    int gga   = (N + 7) / 8;     // 1 warp per node
    const float* Wg[3] = {Wg0, Wg1, Wg2};
    const float* cur = x;
    for (int l = 0; l < 3; l++) {
        gemm_k<128, 8, false><<<gb128, tpb, D * 128 * 4>>>(cur, Wg[l], p_h, N);
        gather_k<<<gga, tpb>>>(p_h, p_x, N);
        cur = p_x;
    }

    // ---- fc1 + fc2/softmax ----
    int gb256 = (N + 31) / 32;   // 8 warps * 4 rows per block
    gemm_k<256, 4, true><<<gb256, tpb, D * 256 * 4>>>(cur, Wfc1, p_y1, N);
    fc2_softmax_k<<<gga, tpb>>>(p_y1, Wfc2, out, N);
}

// round 6
// speedup vs baseline: 1.5987x; 1.1916x over previous
#include <cuda_runtime.h>
#include <math.h>

#define NMAX 50000
#define EMAX 800000
#define D 128
#define NB_SCAN ((NMAX + 1023) / 1024)

// ---------------- scratch (device globals; no allocation allowed) ----------
__device__ int    g_is64;
__device__ int    g_degi[NMAX];
__device__ int    g_off[NMAX + 1];
__device__ int    g_cur[NMAX];
__device__ int    g_bsum[NB_SCAN];
__device__ int    g_bpre[NB_SCAN];
__device__ float  g_dinv[NMAX];
__device__ float2 g_emeta[EMAX];   // {src (bitcast int), norm}
__device__ float  g_h[NMAX * D];
__device__ float  g_x[NMAX * D];
__device__ float  g_y1[NMAX * 256];

// ---------------- f32x2 helpers (Blackwell packed fp32) ---------------------
__device__ __forceinline__ unsigned long long pk2(float lo, float hi) {
    unsigned long long d;
    asm("mov.b64 %0, {%1, %2};" : "=l"(d) : "f"(lo), "f"(hi));
    return d;
}
__device__ __forceinline__ float2 upk2(unsigned long long v) {
    float2 r;
    asm("mov.b64 {%0, %1}, %2;" : "=f"(r.x), "=f"(r.y) : "l"(v));
    return r;
}
__device__ __forceinline__ unsigned long long fma2(unsigned long long a,
                                                   unsigned long long b,
                                                   unsigned long long c) {
    unsigned long long d;
    asm("fma.rn.f32x2 %0, %1, %2, %3;" : "=l"(d) : "l"(a), "l"(b), "l"(c));
    return d;
}

__device__ __forceinline__ float leaky1(float v) {
    return v >= 0.0f ? v : 0.01f * v;
}

// ---------------- edge-index width detection -------------------------------
__global__ void detect_k(const unsigned int* __restrict__ w, int E) {
    __shared__ int nz;
    if (threadIdx.x == 0) nz = 0;
    __syncthreads();
    int n = E < 1024 ? E : 1024;
    for (int i = threadIdx.x; i < n; i += 32)
        if (w[2 * i + 1] != 0u) atomicAdd(&nz, 1);
    __syncthreads();
    if (threadIdx.x == 0) g_is64 = (nz == 0) ? 1 : 0;
}

// ---------------- degree histogram ------------------------------------------
__global__ void count_k(const void* __restrict__ ei, int E) {
    int e = blockIdx.x * blockDim.x + threadIdx.x;
    if (e >= E) return;
    int dst;
    if (g_is64) dst = (int)((const unsigned int*)ei)[2 * (E + e)];
    else        dst = ((const int*)ei)[E + e];
    atomicAdd(&g_degi[dst], 1);
}

__global__ void dinv_k(int N) {
    int i = blockIdx.x * blockDim.x + threadIdx.x;
    if (i < N) g_dinv[i] = rsqrtf((float)g_degi[i] + 1.0f);  // + self loop
}

// ---------------- 3-phase exclusive scan of degrees -> CSR offsets ----------
__global__ void scan1_k(int N) {
    __shared__ int sh[1024];
    int t = threadIdx.x;
    int i = blockIdx.x * 1024 + t;
    int v = (i < N) ? g_degi[i] : 0;
    sh[t] = v;
    __syncthreads();
#pragma unroll
    for (int off = 1; off < 1024; off <<= 1) {
        int u = (t >= off) ? sh[t - off] : 0;
        __syncthreads();
        sh[t] += u;
        __syncthreads();
    }
    if (i < N) g_off[i] = sh[t] - v;            // block-local exclusive
    if (t == 1023) g_bsum[blockIdx.x] = sh[1023];
}

__global__ void scan2_k(int nb) {
    if (threadIdx.x == 0) {
        int run = 0;
        for (int b = 0; b < nb; b++) {
            g_bpre[b] = run;
            run += g_bsum[b];
        }
    }
}

__global__ void scan3_k(int N, int E) {
    int i = blockIdx.x * blockDim.x + threadIdx.x;
    if (i < N) {
        int v = g_off[i] + g_bpre[i >> 10];
        g_off[i] = v;
        g_cur[i] = v;
    }
    if (i == 0) g_off[N] = E;   // sum of degrees == E
}

// ---------------- CSR fill: bucket edges by dst -----------------------------
__global__ void fill_k(const void* __restrict__ ei, int E) {
    int e = blockIdx.x * blockDim.x + threadIdx.x;
    if (e >= E) return;
    int src, dst;
    if (g_is64) {
        src = (int)((const unsigned int*)ei)[2 * e];
        dst = (int)((const unsigned int*)ei)[2 * (E + e)];
    } else {
        src = ((const int*)ei)[e];
        dst = ((const int*)ei)[E + e];
    }
    float norm = g_dinv[src] * g_dinv[dst];
    int p = atomicAdd(&g_cur[dst], 1);
    g_emeta[p] = make_float2(__int_as_float(src), norm);
}

// ---------------- GEMM: H = X @ W  (K = 128), packed f32x2 ------------------
template <int NOUT, int RPW, bool DOLEAKY>
__global__ void gemm_k(const float* __restrict__ X, const float* __restrict__ W,
                       float* __restrict__ H, int N) {
    extern __shared__ float4 Ws4[];  // D*NOUT floats
    const float4* W4 = (const float4*)W;
    for (int i = threadIdx.x; i < D * NOUT / 4; i += blockDim.x) Ws4[i] = W4[i];
    __syncthreads();

    constexpr int C4 = NOUT / 128;   // float4 col chunks per lane
    constexpr int P  = RPW / 2;      // row pairs
    int lane = threadIdx.x & 31;
    int warp_g = blockIdx.x * (blockDim.x >> 5) + (threadIdx.x >> 5);
    int row0 = warp_g * RPW;
    if (row0 >= N) return;

    unsigned long long xp[P][4];
#pragma unroll
    for (int p = 0; p < P; p++) {
        int r0 = row0 + 2 * p, r1 = r0 + 1;
        float4 a = (r0 < N) ? ((const float4*)(X + (size_t)r0 * D))[lane]
                            : make_float4(0.f, 0.f, 0.f, 0.f);
        float4 b = (r1 < N) ? ((const float4*)(X + (size_t)r1 * D))[lane]
                            : make_float4(0.f, 0.f, 0.f, 0.f);
        xp[p][0] = pk2(a.x, b.x);
        xp[p][1] = pk2(a.y, b.y);
        xp[p][2] = pk2(a.z, b.z);
        xp[p][3] = pk2(a.w, b.w);
    }

    unsigned long long acc[P][4 * C4];
#pragma unroll
    for (int p = 0; p < P; p++)
#pragma unroll
        for (int c = 0; c < 4 * C4; c++) acc[p][c] = 0ull;

    for (int sl = 0; sl < 32; ++sl) {
#pragma unroll
        for (int kl = 0; kl < 4; kl++) {
            unsigned long long xs[P];
#pragma unroll
            for (int p = 0; p < P; p++)
                xs[p] = __shfl_sync(0xffffffffu, xp[p][kl], sl);
            int k = sl * 4 + kl;
#pragma unroll
            for (int c = 0; c < C4; c++) {
                float4 wv = Ws4[(size_t)k * (NOUT / 4) + lane + 32 * c];
                unsigned long long w0 = pk2(wv.x, wv.x);
                unsigned long long w1 = pk2(wv.y, wv.y);
                unsigned long long w2 = pk2(wv.z, wv.z);
                unsigned long long w3 = pk2(wv.w, wv.w);
#pragma unroll
                for (int p = 0; p < P; p++) {
                    acc[p][4 * c + 0] = fma2(xs[p], w0, acc[p][4 * c + 0]);
                    acc[p][4 * c + 1] = fma2(xs[p], w1, acc[p][4 * c + 1]);
                    acc[p][4 * c + 2] = fma2(xs[p], w2, acc[p][4 * c + 2]);
                    acc[p][4 * c + 3] = fma2(xs[p], w3, acc[p][4 * c + 3]);
                }
            }
        }
    }

#pragma unroll
    for (int p = 0; p < P; p++) {
        int r0 = row0 + 2 * p, r1 = r0 + 1;
#pragma unroll
        for (int c = 0; c < C4; c++) {
            float2 c0 = upk2(acc[p][4 * c + 0]);
            float2 c1 = upk2(acc[p][4 * c + 1]);
            float2 c2 = upk2(acc[p][4 * c + 2]);
            float2 c3 = upk2(acc[p][4 * c + 3]);
            float4 v0 = make_float4(c0.x, c1.x, c2.x, c3.x);
            float4 v1 = make_float4(c0.y, c1.y, c2.y, c3.y);
            if (DOLEAKY) {
                v0.x = leaky1(v0.x); v0.y = leaky1(v0.y);
                v0.z = leaky1(v0.z); v0.w = leaky1(v0.w);
                v1.x = leaky1(v1.x); v1.y = leaky1(v1.y);
                v1.z = leaky1(v1.z); v1.w = leaky1(v1.w);
            }
            if (r0 < N) ((float4*)(H + (size_t)r0 * NOUT))[lane + 32 * c] = v0;
            if (r1 < N) ((float4*)(H + (size_t)r1 * NOUT))[lane + 32 * c] = v1;
        }
    }
}

// ---------------- gather: X[i] = leaky(dinv_i^2*H[i] + sum norm*H[src]) -----
// One warp per node; lanes hold the 128-float row. 2-way unroll for MLP.
__global__ void gather_k(const float* __restrict__ H, float* __restrict__ X,
                         int N) {
    int lane = threadIdx.x & 31;
    int node = blockIdx.x * (blockDim.x >> 5) + (threadIdx.x >> 5);
    if (node >= N) return;
    int beg = g_off[node], end = g_off[node + 1];
    float s = g_dinv[node];
    float w0 = s * s;
    float4 acc = ((const float4*)(H + (size_t)node * D))[lane];
    acc.x *= w0; acc.y *= w0; acc.z *= w0; acc.w *= w0;

    int j = beg;
    for (; j + 1 < end; j += 2) {
        float2 m0 = g_emeta[j];
        float2 m1 = g_emeta[j + 1];
        int s0 = __float_as_int(m0.x);
        int s1 = __float_as_int(m1.x);
        float4 v0 = ((const float4*)(H + (size_t)s0 * D))[lane];
        float4 v1 = ((const float4*)(H + (size_t)s1 * D))[lane];
        acc.x += m0.y * v0.x + m1.y * v1.x;
        acc.y += m0.y * v0.y + m1.y * v1.y;
        acc.z += m0.y * v0.z + m1.y * v1.z;
        acc.w += m0.y * v0.w + m1.y * v1.w;
    }
    if (j < end) {
        float2 m = g_emeta[j];
        int src = __float_as_int(m.x);
        float w = m.y;
        float4 v = ((const float4*)(H + (size_t)src * D))[lane];
        acc.x += w * v.x; acc.y += w * v.y;
        acc.z += w * v.z; acc.w += w * v.w;
    }
    acc.x = leaky1(acc.x); acc.y = leaky1(acc.y);
    acc.z = leaky1(acc.z); acc.w = leaky1(acc.w);
    ((float4*)(X + (size_t)node * D))[lane] = acc;
}

// ---------------- fc2 (256 -> 2) + leaky + softmax ---------------------------
__global__ void fc2_softmax_k(const float* __restrict__ Y,
                              const float* __restrict__ W2,
                              float* __restrict__ out, int N) {
    __shared__ float w0[256], w1[256];
    for (int i = threadIdx.x; i < 256; i += blockDim.x) {
        w0[i] = W2[i * 2];
        w1[i] = W2[i * 2 + 1];
    }
    __syncthreads();
    int lane = threadIdx.x & 31;
    int node = blockIdx.x * (blockDim.x >> 5) + (threadIdx.x >> 5);
    if (node >= N) return;
    float a0 = 0.f, a1 = 0.f;
#pragma unroll
    for (int i = 0; i < 8; i++) {
        int k = lane + 32 * i;
        float y = Y[(size_t)node * 256 + k];
        a0 += y * w0[k];
        a1 += y * w1[k];
    }
#pragma unroll
    for (int o = 16; o; o >>= 1) {
        a0 += __shfl_xor_sync(0xffffffffu, a0, o);
        a1 += __shfl_xor_sync(0xffffffffu, a1, o);
    }
    if (lane == 0) {
        a0 = leaky1(a0);
        a1 = leaky1(a1);
        float m = fmaxf(a0, a1);
        float e0 = expf(a0 - m), e1 = expf(a1 - m);
        float inv = 1.0f / (e0 + e1);
        out[(size_t)node * 2 + 0] = e0 * inv;
        out[(size_t)node * 2 + 1] = e1 * inv;
    }
}

// ---------------- launch ------------------------------------------------------
extern "C" void kernel_launch(void* const* d_in, const int* in_sizes, int n_in,
                              void* d_out, int out_size) {
    const float* x    = (const float*)d_in[0];
    const void*  ei   = d_in[1];
    const float* Wg0  = (const float*)d_in[2];
    const float* Wg1  = (const float*)d_in[3];
    const float* Wg2  = (const float*)d_in[4];
    const float* Wfc1 = (const float*)d_in[5];
    const float* Wfc2 = (const float*)d_in[6];
    float* out = (float*)d_out;

    int N = in_sizes[0] / D;
    int E = in_sizes[1] / 2;

    float *p_h, *p_x, *p_y1;
    int* p_degi;
    cudaGetSymbolAddress((void**)&p_h, g_h);
    cudaGetSymbolAddress((void**)&p_x, g_x);
    cudaGetSymbolAddress((void**)&p_y1, g_y1);
    cudaGetSymbolAddress((void**)&p_degi, g_degi);

    cudaFuncSetAttribute(gemm_k<128, 8, false>,
                         cudaFuncAttributeMaxDynamicSharedMemorySize,
                         D * 128 * 4);
    cudaFuncSetAttribute(gemm_k<256, 4, true>,
                         cudaFuncAttributeMaxDynamicSharedMemorySize,
                         D * 256 * 4);

    int tpb = 256;
    int gE = (E + tpb - 1) / tpb;
    int gN = (N + tpb - 1) / tpb;
    int nb = (N + 1023) / 1024;

    // ---- CSR build (once per call) ----
    cudaMemsetAsync(p_degi, 0, (size_t)N * sizeof(int));
    detect_k<<<1, 32>>>((const unsigned int*)ei, E);
    count_k<<<gE, tpb>>>(ei, E);
    dinv_k<<<gN, tpb>>>(N);
    scan1_k<<<nb, 1024>>>(N);
    scan2_k<<<1, 32>>>(nb);
    scan3_k<<<gN, tpb>>>(N, E);
    fill_k<<<gE, tpb>>>(ei, E);

    // ---- 3 GCN layers ----
    int gb128 = (N + 63) / 64;   // 8 warps * 8 rows per block
    int gga   = (N + 7) / 8;     // 1 warp per node
    const float* Wg[3] = {Wg0, Wg1, Wg2};
    const float* cur = x;
    for (int l = 0; l < 3; l++) {
        gemm_k<128, 8, false><<<gb128, tpb, D * 128 * 4>>>(cur, Wg[l], p_h, N);
        gather_k<<<gga, tpb>>>(p_h, p_x, N);
        cur = p_x;
    }

    // ---- fc1 + fc2/softmax ----
    int gb256 = (N + 31) / 32;   // 8 warps * 4 rows per block
    gemm_k<256, 4, true><<<gb256, tpb, D * 256 * 4>>>(cur, Wfc1, p_y1, N);
    fc2_softmax_k<<<gga, tpb>>>(p_y1, Wfc2, out, N);
}